// round 3
// baseline (speedup 1.0000x reference)
#include <cuda_runtime.h>
#include <cuda_bf16.h>
#include <cstdint>

#define Tt 2048
#define Dd 512
#define BHn 16
#define QKV_ELEMS 16777216u
#define S_ELEMS   67108864u

// ---------------- scratch (device globals) ----------------
__device__ __nv_bfloat16 g_Qh[QKV_ELEMS], g_Ql[QKV_ELEMS];
__device__ __nv_bfloat16 g_Kh[QKV_ELEMS], g_Kl[QKV_ELEMS];
__device__ __nv_bfloat16 g_Vth[QKV_ELEMS], g_Vtl[QKV_ELEMS];
__device__ __nv_bfloat16 g_Ph[S_ELEMS],  g_Pl[S_ELEMS];
__device__ float g_S[S_ELEMS];

// ---------------- helpers ----------------
__device__ __forceinline__ void ldm4(unsigned* r, const void* p) {
    unsigned a = (unsigned)__cvta_generic_to_shared(p);
    asm volatile("ldmatrix.sync.aligned.m8n8.x4.shared.b16 {%0,%1,%2,%3}, [%4];"
                 : "=r"(r[0]), "=r"(r[1]), "=r"(r[2]), "=r"(r[3]) : "r"(a));
}
__device__ __forceinline__ void mma16816(float* c, const unsigned* a, unsigned b0, unsigned b1) {
    asm volatile(
        "mma.sync.aligned.m16n8k16.row.col.f32.bf16.bf16.f32 "
        "{%0,%1,%2,%3},{%4,%5,%6,%7},{%8,%9},{%0,%1,%2,%3};\n"
        : "+f"(c[0]), "+f"(c[1]), "+f"(c[2]), "+f"(c[3])
        : "r"(a[0]), "r"(a[1]), "r"(a[2]), "r"(a[3]), "r"(b0), "r"(b1));
}
__device__ __forceinline__ void cpasync16(void* s, const void* g) {
    unsigned sa = (unsigned)__cvta_generic_to_shared(s);
    asm volatile("cp.async.cg.shared.global [%0], [%1], 16;" :: "r"(sa), "l"(g));
}
#define CP_COMMIT() asm volatile("cp.async.commit_group;" ::: "memory")
#define CP_WAIT2()  asm volatile("cp.async.wait_group 2;" ::: "memory")

// ---------------- convert Q,K into hi/lo planes ----------------
__global__ void convert_qk(const float* __restrict__ Q, const float* __restrict__ K,
                           const float* __restrict__ route) {
    unsigned i = blockIdx.x * 256u + threadIdx.x;
    int d = (int)(i & (Dd - 1));
    int b = (int)(i >> 23);
    float g = route[b * 8 + (d >> 6)] * 0.125f;      // gate * 1/sqrt(64)
    float q = Q[i] * g;
    __nv_bfloat16 h = __float2bfloat16(q);
    g_Qh[i] = h; g_Ql[i] = __float2bfloat16(q - __bfloat162float(h));
    float k = K[i];
    h = __float2bfloat16(k);
    g_Kh[i] = h; g_Kl[i] = __float2bfloat16(k - __bfloat162float(h));
}

// ---------------- transpose V -> Vt planes ----------------
__global__ void convert_vt(const float* __restrict__ V) {
    __shared__ float tile[32][33];
    int bh = blockIdx.z, t0 = blockIdx.x * 32, d0 = blockIdx.y * 32;
    int tx = threadIdx.x & 31, ty = threadIdx.x >> 5;
    const float* Vb = V + (size_t)bh * Tt * Dd;
#pragma unroll
    for (int j = 0; j < 4; j++)
        tile[ty + j * 8][tx] = Vb[(size_t)(t0 + ty + j * 8) * Dd + d0 + tx];
    __syncthreads();
#pragma unroll
    for (int j = 0; j < 4; j++) {
        int d = d0 + ty + j * 8, tt = t0 + tx;
        float v = tile[tx][ty + j * 8];
        __nv_bfloat16 h = __float2bfloat16(v);
        size_t o = (size_t)bh * Dd * Tt + (size_t)d * Tt + tt;
        g_Vth[o] = h;
        g_Vtl[o] = __float2bfloat16(v - __bfloat162float(h));
    }
}

// ---------------- pipelined NT split-bf16 GEMM, CTA 128x128x32 ----------------
// EPI==0: S = Qg * K^T   (fp32 -> g_S)
// EPI==1: out = P * Vt^T (* gate, fp32 -> d_out)
#define PS 40                     // smem row stride in elements (80B, 16B-aligned)
#define PLANE_B (128 * PS * 2)    // 10240 bytes per plane
#define OFF_AH 0
#define OFF_AL (PLANE_B)
#define OFF_BH (2 * PLANE_B)
#define OFF_BL (3 * PLANE_B)
#define STAGE_B (4 * PLANE_B)     // 40960
#define NSTAGE 4
#define SMEM_DYN (NSTAGE * STAGE_B)

template<int EPI>
__global__ __launch_bounds__(512, 1) void gemm_nt(float* __restrict__ outp,
                                                  const float* __restrict__ route) {
    constexpr int Kd  = EPI ? Tt : Dd;
    constexpr int lda = Kd;
    constexpr int ldb = Kd;
    constexpr int ldc = EPI ? Dd : Tt;
    constexpr int KT  = Kd / 32;

    extern __shared__ __align__(16) char sm[];

    const int bh = blockIdx.z;
    const int m0 = blockIdx.y * 128;
    const int n0 = blockIdx.x * 128;
    const int t = threadIdx.x, lane = t & 31, warp = t >> 5;
    const int wm = warp & 3, wn = warp >> 2;     // 4x4 warp grid, warp tile 32x32
    const int lrow = lane & 15;
    const int lko  = (lane >> 4) << 3;

    const __nv_bfloat16* gAh = (EPI ? g_Ph : g_Qh) + (size_t)bh * Tt * lda + (size_t)m0 * lda;
    const __nv_bfloat16* gAl = (EPI ? g_Pl : g_Ql) + (size_t)bh * Tt * lda + (size_t)m0 * lda;
    const __nv_bfloat16* gBh = (EPI ? g_Vth : g_Kh) + (size_t)bh * (size_t)(EPI ? Dd : Tt) * ldb + (size_t)n0 * ldb;
    const __nv_bfloat16* gBl = (EPI ? g_Vtl : g_Kl) + (size_t)bh * (size_t)(EPI ? Dd : Tt) * ldb + (size_t)n0 * ldb;

    // per-thread load slot: row 0..127, k-chunk 0..3 (8 elems = 16B)
    const int arow = t >> 2, kc = t & 3;
    const size_t goff = (size_t)arow * lda + kc * 8;   // lda == ldb
    const int soff = arow * (PS * 2) + kc * 16;        // bytes

    unsigned short* sAh_all = (unsigned short*)(sm + OFF_AH);
    (void)sAh_all;

    float acc[2][4][4];
#pragma unroll
    for (int a = 0; a < 2; a++)
#pragma unroll
        for (int b = 0; b < 4; b++)
#pragma unroll
            for (int c = 0; c < 4; c++) acc[a][b][c] = 0.f;

    // ---- prologue: issue stages 0..2 ----
#pragma unroll
    for (int p = 0; p < 3; p++) {
        if (p < KT) {
            char* stg = sm + (p & (NSTAGE - 1)) * STAGE_B;
            const size_t ko = (size_t)p * 32;
            cpasync16(stg + OFF_AH + soff, gAh + goff + ko);
            cpasync16(stg + OFF_AL + soff, gAl + goff + ko);
            cpasync16(stg + OFF_BH + soff, gBh + goff + ko);
            cpasync16(stg + OFF_BL + soff, gBl + goff + ko);
        }
        CP_COMMIT();
    }

    for (int kt = 0; kt < KT; kt++) {
        CP_WAIT2();
        __syncthreads();

        // issue stage kt+3
        if (kt + 3 < KT) {
            char* stg = sm + ((kt + 3) & (NSTAGE - 1)) * STAGE_B;
            const size_t ko = (size_t)(kt + 3) * 32;
            cpasync16(stg + OFF_AH + soff, gAh + goff + ko);
            cpasync16(stg + OFF_AL + soff, gAl + goff + ko);
            cpasync16(stg + OFF_BH + soff, gBh + goff + ko);
            cpasync16(stg + OFF_BL + soff, gBl + goff + ko);
        }
        CP_COMMIT();

        // compute stage kt
        char* stg = sm + (kt & (NSTAGE - 1)) * STAGE_B;
        unsigned short* sAh = (unsigned short*)(stg + OFF_AH);
        unsigned short* sAl = (unsigned short*)(stg + OFF_AL);
        unsigned short* sBh = (unsigned short*)(stg + OFF_BH);
        unsigned short* sBl = (unsigned short*)(stg + OFF_BL);

#pragma unroll
        for (int ks = 0; ks < 2; ks++) {
            int kb = ks * 16 + lko;
            unsigned ah[2][4], al[2][4], bhr[2][4], blr[2][4];
#pragma unroll
            for (int mt = 0; mt < 2; mt++) {
                int r = (wm * 32 + mt * 16 + lrow) * PS + kb;
                ldm4(ah[mt], &sAh[r]);
                ldm4(al[mt], &sAl[r]);
            }
#pragma unroll
            for (int nb = 0; nb < 2; nb++) {
                int r = (wn * 32 + nb * 16 + lrow) * PS + kb;
                ldm4(bhr[nb], &sBh[r]);
                ldm4(blr[nb], &sBl[r]);
            }
#pragma unroll
            for (int mt = 0; mt < 2; mt++)
#pragma unroll
                for (int nt = 0; nt < 4; nt++) {
                    int nb = nt >> 1, o = nt & 1;
                    mma16816(acc[mt][nt], ah[mt], bhr[nb][o], bhr[nb][o + 2]);
                    mma16816(acc[mt][nt], ah[mt], blr[nb][o], blr[nb][o + 2]);
                    mma16816(acc[mt][nt], al[mt], bhr[nb][o], bhr[nb][o + 2]);
                }
        }
    }

    // ---- epilogue ----
    float* Cp = EPI ? (outp + (size_t)bh * Tt * Dd) : (g_S + (size_t)bh * Tt * Tt);
    int rbase = m0 + wm * 32 + (lane >> 2);
    int cbase = n0 + wn * 32 + (lane & 3) * 2;
    float scl = 1.f;
    if (EPI) scl = route[(bh >> 3) * 8 + ((n0 + wn * 32) >> 6)];
#pragma unroll
    for (int mt = 0; mt < 2; mt++)
#pragma unroll
        for (int nt = 0; nt < 4; nt++) {
            int r = rbase + mt * 16;
            int c = cbase + nt * 8;
            float2 v0 = make_float2(acc[mt][nt][0] * scl, acc[mt][nt][1] * scl);
            float2 v1 = make_float2(acc[mt][nt][2] * scl, acc[mt][nt][3] * scl);
            *(float2*)&Cp[(size_t)r       * ldc + c] = v0;
            *(float2*)&Cp[(size_t)(r + 8) * ldc + c] = v1;
        }
}

// ---------------- masked row softmax: fp32 S -> Ph/Pl planes ----------------
__global__ __launch_bounds__(256) void softmax_rows(const int* __restrict__ mask) {
    int row = blockIdx.x;
    int q = row & (Tt - 1);
    const float* Srow = g_S + (size_t)row * Tt;
    const int* mrow = mask + (size_t)q * Tt;
    int t = threadIdx.x;
    int lane = t & 31, warp = t >> 5;

    float s[8];
#pragma unroll
    for (int j = 0; j < 8; j++) {
        int k = t + j * 256;
        s[j] = mrow[k] ? -INFINITY : Srow[k];
    }
    float mx = s[0];
#pragma unroll
    for (int j = 1; j < 8; j++) mx = fmaxf(mx, s[j]);
#pragma unroll
    for (int o = 16; o; o >>= 1) mx = fmaxf(mx, __shfl_xor_sync(0xFFFFFFFFu, mx, o));
    __shared__ float red[8];
    if (lane == 0) red[warp] = mx;
    __syncthreads();
    float mall = red[0];
#pragma unroll
    for (int w = 1; w < 8; w++) mall = fmaxf(mall, red[w]);

    float e[8], sum = 0.f;
#pragma unroll
    for (int j = 0; j < 8; j++) {
        e[j] = (s[j] == -INFINITY) ? 0.f : expf(s[j] - mall);
        sum += e[j];
    }
#pragma unroll
    for (int o = 16; o; o >>= 1) sum += __shfl_xor_sync(0xFFFFFFFFu, sum, o);
    __syncthreads();
    if (lane == 0) red[warp] = sum;
    __syncthreads();
    float tot = 0.f;
#pragma unroll
    for (int w = 0; w < 8; w++) tot += red[w];
    float inv = tot > 0.f ? 1.f / tot : 0.f;

#pragma unroll
    for (int j = 0; j < 8; j++) {
        int k = t + j * 256;
        float p = e[j] * inv;
        __nv_bfloat16 h = __float2bfloat16(p);
        size_t o = (size_t)row * Tt + k;
        g_Ph[o] = h;
        g_Pl[o] = __float2bfloat16(p - __bfloat162float(h));
    }
}

// ---------------- launch ----------------
extern "C" void kernel_launch(void* const* d_in, const int* in_sizes, int n_in,
                              void* d_out, int out_size) {
    const float* Q     = (const float*)d_in[0];
    const float* K     = (const float*)d_in[1];
    const float* V     = (const float*)d_in[2];
    const float* route = (const float*)d_in[3];
    const int*   mask  = (const int*)d_in[5];
    float* out = (float*)d_out;

    cudaFuncSetAttribute(gemm_nt<0>, cudaFuncAttributeMaxDynamicSharedMemorySize, SMEM_DYN);
    cudaFuncSetAttribute(gemm_nt<1>, cudaFuncAttributeMaxDynamicSharedMemorySize, SMEM_DYN);

    convert_qk<<<QKV_ELEMS / 256, 256>>>(Q, K, route);
    convert_vt<<<dim3(Tt / 32, Dd / 32, BHn), 256>>>(V);
    gemm_nt<0><<<dim3(Tt / 128, Tt / 128, BHn), 512, SMEM_DYN>>>(nullptr, route);
    softmax_rows<<<BHn * Tt, 256>>>(mask);
    gemm_nt<1><<<dim3(Dd / 128, Tt / 128, BHn), 512, SMEM_DYN>>>(out, route);
}

// round 4
// speedup vs baseline: 1.4423x; 1.4423x over previous
#include <cuda_runtime.h>
#include <cuda_fp16.h>
#include <cstdint>

#define Tt 2048
#define Dd 512
#define BHn 16
#define QKV_ELEMS 16777216u
#define S_ELEMS   67108864u

// ---------------- scratch (device globals) ----------------
__device__ __half g_Qh[QKV_ELEMS], g_Ql[QKV_ELEMS];
__device__ __half g_Kh[QKV_ELEMS], g_Kl[QKV_ELEMS];
__device__ __half g_Vt[QKV_ELEMS];
__device__ __half g_P [S_ELEMS];
__device__ float  g_S [S_ELEMS];

// ---------------- helpers ----------------
__device__ __forceinline__ void ldm4(unsigned* r, const void* p) {
    unsigned a = (unsigned)__cvta_generic_to_shared(p);
    asm volatile("ldmatrix.sync.aligned.m8n8.x4.shared.b16 {%0,%1,%2,%3}, [%4];"
                 : "=r"(r[0]), "=r"(r[1]), "=r"(r[2]), "=r"(r[3]) : "r"(a));
}
__device__ __forceinline__ void mmah(float* c, const unsigned* a, unsigned b0, unsigned b1) {
    asm volatile(
        "mma.sync.aligned.m16n8k16.row.col.f32.f16.f16.f32 "
        "{%0,%1,%2,%3},{%4,%5,%6,%7},{%8,%9},{%0,%1,%2,%3};\n"
        : "+f"(c[0]), "+f"(c[1]), "+f"(c[2]), "+f"(c[3])
        : "r"(a[0]), "r"(a[1]), "r"(a[2]), "r"(a[3]), "r"(b0), "r"(b1));
}
__device__ __forceinline__ void cpasync16(void* s, const void* g) {
    unsigned sa = (unsigned)__cvta_generic_to_shared(s);
    asm volatile("cp.async.cg.shared.global [%0], [%1], 16;" :: "r"(sa), "l"(g));
}
#define CP_COMMIT() asm volatile("cp.async.commit_group;" ::: "memory")
#define CP_WAIT2()  asm volatile("cp.async.wait_group 2;" ::: "memory")

// ---------------- convert Q,K into fp16 planes ----------------
__global__ void convert_qk(const float* __restrict__ Q, const float* __restrict__ K,
                           const float* __restrict__ route) {
    unsigned i = blockIdx.x * 256u + threadIdx.x;
    int d = (int)(i & (Dd - 1));
    int b = (int)(i >> 23);
    float g = route[b * 8 + (d >> 6)] * 0.125f;      // gate * 1/sqrt(64)
    float q = Q[i] * g;
    __half h = __float2half_rn(q);
    g_Qh[i] = h; g_Ql[i] = __float2half_rn(q - __half2float(h));
    float k = K[i];
    h = __float2half_rn(k);
    g_Kh[i] = h; g_Kl[i] = __float2half_rn(k - __half2float(h));
}

// ---------------- transpose V -> Vt fp16 ----------------
__global__ void convert_vt(const float* __restrict__ V) {
    __shared__ float tile[32][33];
    int bh = blockIdx.z, t0 = blockIdx.x * 32, d0 = blockIdx.y * 32;
    int tx = threadIdx.x & 31, ty = threadIdx.x >> 5;
    const float* Vb = V + (size_t)bh * Tt * Dd;
#pragma unroll
    for (int j = 0; j < 4; j++)
        tile[ty + j * 8][tx] = Vb[(size_t)(t0 + ty + j * 8) * Dd + d0 + tx];
    __syncthreads();
#pragma unroll
    for (int j = 0; j < 4; j++) {
        int d = d0 + ty + j * 8, tt = t0 + tx;
        g_Vt[(size_t)bh * Dd * Tt + (size_t)d * Tt + tt] = __float2half_rn(tile[tx][ty + j * 8]);
    }
}

// ---------------- GEMM1: S = Qg * K^T, fp16 split-A + adaptive K-lo term ----------------
#define PS 40
#define PLANE_B (128 * PS * 2)       // 10240
#define G1_AH 0
#define G1_AL (PLANE_B)
#define G1_BH (2 * PLANE_B)
#define G1_BL (3 * PLANE_B)
#define G1_STAGE (4 * PLANE_B)       // 40960
#define NSTAGE 4
#define G1_SMEM (NSTAGE * G1_STAGE)  // 163840

__global__ __launch_bounds__(512, 1) void gemm1(const float* __restrict__ route) {
    constexpr int lda = Dd, KT = Dd / 32;
    extern __shared__ __align__(16) char sm[];

    const int bh = blockIdx.z;
    const int m0 = blockIdx.y * 128;
    const int n0 = blockIdx.x * 128;
    const int t = threadIdx.x, lane = t & 31, warp = t >> 5;
    const int wm = warp & 3, wn = warp >> 2;
    const int lrow = lane & 15, lko = (lane >> 4) << 3;

    const __half* gAh = g_Qh + (size_t)bh * Tt * lda + (size_t)m0 * lda;
    const __half* gAl = g_Ql + (size_t)bh * Tt * lda + (size_t)m0 * lda;
    const __half* gBh = g_Kh + (size_t)bh * Tt * lda + (size_t)n0 * lda;
    const __half* gBl = g_Kl + (size_t)bh * Tt * lda + (size_t)n0 * lda;
    const float* rb = route + (bh >> 3) * 8;

    const int arow = t >> 2, kc = t & 3;
    const size_t goff = (size_t)arow * lda + kc * 8;
    const int soff = arow * (PS * 2) + kc * 16;

    float acc[2][4][4];
#pragma unroll
    for (int a = 0; a < 2; a++)
#pragma unroll
        for (int b = 0; b < 4; b++)
#pragma unroll
            for (int c = 0; c < 4; c++) acc[a][b][c] = 0.f;

#pragma unroll
    for (int p = 0; p < 3; p++) {
        char* stg = sm + p * G1_STAGE;
        const size_t ko = (size_t)p * 32;
        cpasync16(stg + G1_AH + soff, gAh + goff + ko);
        cpasync16(stg + G1_AL + soff, gAl + goff + ko);
        cpasync16(stg + G1_BH + soff, gBh + goff + ko);
        cpasync16(stg + G1_BL + soff, gBl + goff + ko);
        CP_COMMIT();
    }

    for (int kt = 0; kt < KT; kt++) {
        CP_WAIT2();
        __syncthreads();
        if (kt + 3 < KT) {
            char* stg = sm + ((kt + 3) & (NSTAGE - 1)) * G1_STAGE;
            const size_t ko = (size_t)(kt + 3) * 32;
            cpasync16(stg + G1_AH + soff, gAh + goff + ko);
            cpasync16(stg + G1_AL + soff, gAl + goff + ko);
            cpasync16(stg + G1_BH + soff, gBh + goff + ko);
            cpasync16(stg + G1_BL + soff, gBl + goff + ko);
        }
        CP_COMMIT();

        char* stg = sm + (kt & (NSTAGE - 1)) * G1_STAGE;
        unsigned short* sAh = (unsigned short*)(stg + G1_AH);
        unsigned short* sAl = (unsigned short*)(stg + G1_AL);
        unsigned short* sBh = (unsigned short*)(stg + G1_BH);
        unsigned short* sBl = (unsigned short*)(stg + G1_BL);

        const bool t3 = rb[kt >> 1] > 0.5f;   // expert block of this k-tile

#pragma unroll
        for (int ks = 0; ks < 2; ks++) {
            int kb = ks * 16 + lko;
            unsigned ah[2][4], al[2][4], bh[2][4];
#pragma unroll
            for (int mt = 0; mt < 2; mt++) {
                int r = (wm * 32 + mt * 16 + lrow) * PS + kb;
                ldm4(ah[mt], &sAh[r]);
                ldm4(al[mt], &sAl[r]);
            }
#pragma unroll
            for (int nb = 0; nb < 2; nb++) {
                int r = (wn * 32 + nb * 16 + lrow) * PS + kb;
                ldm4(bh[nb], &sBh[r]);
            }
#pragma unroll
            for (int mt = 0; mt < 2; mt++)
#pragma unroll
                for (int nt = 0; nt < 4; nt++) {
                    int nb = nt >> 1, o = nt & 1;
                    mmah(acc[mt][nt], ah[mt], bh[nb][o], bh[nb][o + 2]);
                    mmah(acc[mt][nt], al[mt], bh[nb][o], bh[nb][o + 2]);
                }
            if (t3) {
                unsigned bl[2][4];
#pragma unroll
                for (int nb = 0; nb < 2; nb++) {
                    int r = (wn * 32 + nb * 16 + lrow) * PS + kb;
                    ldm4(bl[nb], &sBl[r]);
                }
#pragma unroll
                for (int mt = 0; mt < 2; mt++)
#pragma unroll
                    for (int nt = 0; nt < 4; nt++) {
                        int nb = nt >> 1, o = nt & 1;
                        mmah(acc[mt][nt], ah[mt], bl[nb][o], bl[nb][o + 2]);
                    }
            }
        }
    }

    float* Cp = g_S + (size_t)bh * Tt * Tt;
    int rbase = m0 + wm * 32 + (lane >> 2);
    int cbase = n0 + wn * 32 + (lane & 3) * 2;
#pragma unroll
    for (int mt = 0; mt < 2; mt++)
#pragma unroll
        for (int nt = 0; nt < 4; nt++) {
            int r = rbase + mt * 16, c = cbase + nt * 8;
            *(float2*)&Cp[(size_t)r       * Tt + c] = make_float2(acc[mt][nt][0], acc[mt][nt][1]);
            *(float2*)&Cp[(size_t)(r + 8) * Tt + c] = make_float2(acc[mt][nt][2], acc[mt][nt][3]);
        }
}

// ---------------- GEMM2: out = P * Vt^T (* gate), plain fp16 ----------------
#define G2_AH 0
#define G2_BH (PLANE_B)
#define G2_STAGE (2 * PLANE_B)       // 20480
#define G2_SMEM (NSTAGE * G2_STAGE)  // 81920

__global__ __launch_bounds__(512, 1) void gemm2(float* __restrict__ outp,
                                                const float* __restrict__ route) {
    constexpr int lda = Tt, KT = Tt / 32;
    extern __shared__ __align__(16) char sm[];

    const int bh = blockIdx.z;
    const int m0 = blockIdx.y * 128;
    const int n0 = blockIdx.x * 128;
    const int t = threadIdx.x, lane = t & 31, warp = t >> 5;
    const int wm = warp & 3, wn = warp >> 2;
    const int lrow = lane & 15, lko = (lane >> 4) << 3;

    const __half* gA = g_P  + (size_t)bh * Tt * lda + (size_t)m0 * lda;
    const __half* gB = g_Vt + (size_t)bh * Dd * lda + (size_t)n0 * lda;

    const int arow = t >> 2, kc = t & 3;
    const size_t goff = (size_t)arow * lda + kc * 8;
    const int soff = arow * (PS * 2) + kc * 16;

    float acc[2][4][4];
#pragma unroll
    for (int a = 0; a < 2; a++)
#pragma unroll
        for (int b = 0; b < 4; b++)
#pragma unroll
            for (int c = 0; c < 4; c++) acc[a][b][c] = 0.f;

#pragma unroll
    for (int p = 0; p < 3; p++) {
        char* stg = sm + p * G2_STAGE;
        const size_t ko = (size_t)p * 32;
        cpasync16(stg + G2_AH + soff, gA + goff + ko);
        cpasync16(stg + G2_BH + soff, gB + goff + ko);
        CP_COMMIT();
    }

    for (int kt = 0; kt < KT; kt++) {
        CP_WAIT2();
        __syncthreads();
        if (kt + 3 < KT) {
            char* stg = sm + ((kt + 3) & (NSTAGE - 1)) * G2_STAGE;
            const size_t ko = (size_t)(kt + 3) * 32;
            cpasync16(stg + G2_AH + soff, gA + goff + ko);
            cpasync16(stg + G2_BH + soff, gB + goff + ko);
        }
        CP_COMMIT();

        char* stg = sm + (kt & (NSTAGE - 1)) * G2_STAGE;
        unsigned short* sA = (unsigned short*)(stg + G2_AH);
        unsigned short* sB = (unsigned short*)(stg + G2_BH);

#pragma unroll
        for (int ks = 0; ks < 2; ks++) {
            int kb = ks * 16 + lko;
            unsigned af[2][4], bf[2][4];
#pragma unroll
            for (int mt = 0; mt < 2; mt++) {
                int r = (wm * 32 + mt * 16 + lrow) * PS + kb;
                ldm4(af[mt], &sA[r]);
            }
#pragma unroll
            for (int nb = 0; nb < 2; nb++) {
                int r = (wn * 32 + nb * 16 + lrow) * PS + kb;
                ldm4(bf[nb], &sB[r]);
            }
#pragma unroll
            for (int mt = 0; mt < 2; mt++)
#pragma unroll
                for (int nt = 0; nt < 4; nt++) {
                    int nb = nt >> 1, o = nt & 1;
                    mmah(acc[mt][nt], af[mt], bf[nb][o], bf[nb][o + 2]);
                }
        }
    }

    float* Cp = outp + (size_t)bh * Tt * Dd;
    int rbase = m0 + wm * 32 + (lane >> 2);
    int cbase = n0 + wn * 32 + (lane & 3) * 2;
    float scl = route[(bh >> 3) * 8 + ((n0 + wn * 32) >> 6)];
#pragma unroll
    for (int mt = 0; mt < 2; mt++)
#pragma unroll
        for (int nt = 0; nt < 4; nt++) {
            int r = rbase + mt * 16, c = cbase + nt * 8;
            *(float2*)&Cp[(size_t)r       * Dd + c] = make_float2(acc[mt][nt][0] * scl, acc[mt][nt][1] * scl);
            *(float2*)&Cp[(size_t)(r + 8) * Dd + c] = make_float2(acc[mt][nt][2] * scl, acc[mt][nt][3] * scl);
        }
}

// ---------------- masked row softmax: fp32 S -> fp16 P ----------------
__global__ __launch_bounds__(256) void softmax_rows(const int* __restrict__ mask) {
    int row = blockIdx.x;
    int q = row & (Tt - 1);
    const float* Srow = g_S + (size_t)row * Tt;
    const int* mrow = mask + (size_t)q * Tt;
    int t = threadIdx.x;
    int lane = t & 31, warp = t >> 5;

    float s[8];
#pragma unroll
    for (int j = 0; j < 8; j++) {
        int k = t + j * 256;
        s[j] = mrow[k] ? -INFINITY : Srow[k];
    }
    float mx = s[0];
#pragma unroll
    for (int j = 1; j < 8; j++) mx = fmaxf(mx, s[j]);
#pragma unroll
    for (int o = 16; o; o >>= 1) mx = fmaxf(mx, __shfl_xor_sync(0xFFFFFFFFu, mx, o));
    __shared__ float red[8];
    if (lane == 0) red[warp] = mx;
    __syncthreads();
    float mall = red[0];
#pragma unroll
    for (int w = 1; w < 8; w++) mall = fmaxf(mall, red[w]);

    float e[8], sum = 0.f;
#pragma unroll
    for (int j = 0; j < 8; j++) {
        e[j] = (s[j] == -INFINITY) ? 0.f : expf(s[j] - mall);
        sum += e[j];
    }
#pragma unroll
    for (int o = 16; o; o >>= 1) sum += __shfl_xor_sync(0xFFFFFFFFu, sum, o);
    __syncthreads();
    if (lane == 0) red[warp] = sum;
    __syncthreads();
    float tot = 0.f;
#pragma unroll
    for (int w = 0; w < 8; w++) tot += red[w];
    float inv = tot > 0.f ? 1.f / tot : 0.f;

#pragma unroll
    for (int j = 0; j < 8; j++) {
        int k = t + j * 256;
        g_P[(size_t)row * Tt + k] = __float2half_rn(e[j] * inv);
    }
}

// ---------------- launch ----------------
extern "C" void kernel_launch(void* const* d_in, const int* in_sizes, int n_in,
                              void* d_out, int out_size) {
    const float* Q     = (const float*)d_in[0];
    const float* K     = (const float*)d_in[1];
    const float* V     = (const float*)d_in[2];
    const float* route = (const float*)d_in[3];
    const int*   mask  = (const int*)d_in[5];
    float* out = (float*)d_out;

    cudaFuncSetAttribute(gemm1, cudaFuncAttributeMaxDynamicSharedMemorySize, G1_SMEM);
    cudaFuncSetAttribute(gemm2, cudaFuncAttributeMaxDynamicSharedMemorySize, G2_SMEM);

    convert_qk<<<QKV_ELEMS / 256, 256>>>(Q, K, route);
    convert_vt<<<dim3(Tt / 32, Dd / 32, BHn), 256>>>(V);
    gemm1<<<dim3(Tt / 128, Tt / 128, BHn), 512, G1_SMEM>>>(route);
    softmax_rows<<<BHn * Tt, 256>>>(mask);
    gemm2<<<dim3(Dd / 128, Tt / 128, BHn), 512, G2_SMEM>>>(out, route);
}

// round 5
// speedup vs baseline: 2.2650x; 1.5704x over previous
#include <cuda_runtime.h>
#include <cuda_fp16.h>
#include <cstdint>

#define Tt 2048
#define Dd 512
#define BHn 16
#define QKV_ELEMS 16777216u
#define S_ELEMS   67108864u

// ---------------- scratch (device globals) ----------------
__device__ __half g_Qh[QKV_ELEMS];
__device__ __half g_Kh[QKV_ELEMS];
__device__ __half g_Vt[QKV_ELEMS];
__device__ __half g_P [S_ELEMS];
__device__ float  g_S [S_ELEMS];

// ---------------- helpers ----------------
__device__ __forceinline__ void ldm4(unsigned* r, const void* p) {
    unsigned a = (unsigned)__cvta_generic_to_shared(p);
    asm volatile("ldmatrix.sync.aligned.m8n8.x4.shared.b16 {%0,%1,%2,%3}, [%4];"
                 : "=r"(r[0]), "=r"(r[1]), "=r"(r[2]), "=r"(r[3]) : "r"(a));
}
__device__ __forceinline__ void mmah(float* c, const unsigned* a, unsigned b0, unsigned b1) {
    asm volatile(
        "mma.sync.aligned.m16n8k16.row.col.f32.f16.f16.f32 "
        "{%0,%1,%2,%3},{%4,%5,%6,%7},{%8,%9},{%0,%1,%2,%3};\n"
        : "+f"(c[0]), "+f"(c[1]), "+f"(c[2]), "+f"(c[3])
        : "r"(a[0]), "r"(a[1]), "r"(a[2]), "r"(a[3]), "r"(b0), "r"(b1));
}
__device__ __forceinline__ void cpasync16(void* s, const void* g) {
    unsigned sa = (unsigned)__cvta_generic_to_shared(s);
    asm volatile("cp.async.cg.shared.global [%0], [%1], 16;" :: "r"(sa), "l"(g));
}
#define CP_COMMIT() asm volatile("cp.async.commit_group;" ::: "memory")
#define CP_WAIT2()  asm volatile("cp.async.wait_group 2;" ::: "memory")

// ---------------- convert Q,K to fp16 (gate & 1/sqrt(64) folded into Q) ----------------
__global__ void convert_qk(const float* __restrict__ Q, const float* __restrict__ K,
                           const float* __restrict__ route) {
    unsigned i = blockIdx.x * 256u + threadIdx.x;
    int d = (int)(i & (Dd - 1));
    int b = (int)(i >> 23);
    float g = route[b * 8 + (d >> 6)] * 0.125f;
    g_Qh[i] = __float2half_rn(Q[i] * g);
    g_Kh[i] = __float2half_rn(K[i]);
}

// ---------------- transpose V -> Vt fp16 ----------------
__global__ void convert_vt(const float* __restrict__ V) {
    __shared__ float tile[32][33];
    int bh = blockIdx.z, t0 = blockIdx.x * 32, d0 = blockIdx.y * 32;
    int tx = threadIdx.x & 31, ty = threadIdx.x >> 5;
    const float* Vb = V + (size_t)bh * Tt * Dd;
#pragma unroll
    for (int j = 0; j < 4; j++)
        tile[ty + j * 8][tx] = Vb[(size_t)(t0 + ty + j * 8) * Dd + d0 + tx];
    __syncthreads();
#pragma unroll
    for (int j = 0; j < 4; j++) {
        int d = d0 + ty + j * 8, tt = t0 + tx;
        g_Vt[(size_t)bh * Dd * Tt + (size_t)d * Tt + tt] = __float2half_rn(tile[tx][ty + j * 8]);
    }
}

// ---------------- pipelined NT fp16 GEMM, CTA 128x128x32, 1 MMA term ----------------
// EPI==0: S = Qg * K^T   (fp32 -> g_S)
// EPI==1: out = P * Vt^T (* gate, fp32 -> d_out)
#define PS 40
#define PLANE_B (128 * PS * 2)       // 10240 bytes
#define G_AH 0
#define G_BH (PLANE_B)
#define G_STAGE (2 * PLANE_B)        // 20480
#define NSTAGE 4
#define G_SMEM (NSTAGE * G_STAGE)    // 81920

template<int EPI>
__global__ __launch_bounds__(512, 1) void gemm_nt(float* __restrict__ outp,
                                                  const float* __restrict__ route) {
    constexpr int Kd  = EPI ? Tt : Dd;
    constexpr int lda = Kd;
    constexpr int ldc = EPI ? Dd : Tt;
    constexpr int KT  = Kd / 32;

    extern __shared__ __align__(16) char sm[];

    const int bh = blockIdx.z;
    const int m0 = blockIdx.y * 128;
    const int n0 = blockIdx.x * 128;
    const int t = threadIdx.x, lane = t & 31, warp = t >> 5;
    const int wm = warp & 3, wn = warp >> 2;     // 4x4 warp grid, warp tile 32x32
    const int lrow = lane & 15, lko = (lane >> 4) << 3;

    const __half* gA = (EPI ? g_P  : g_Qh) + (size_t)bh * Tt * lda + (size_t)m0 * lda;
    const __half* gB = (EPI ? g_Vt : g_Kh) + (size_t)bh * (size_t)(EPI ? Dd : Tt) * lda + (size_t)n0 * lda;

    const int arow = t >> 2, kc = t & 3;
    const size_t goff = (size_t)arow * lda + kc * 8;
    const int soff = arow * (PS * 2) + kc * 16;

    float acc[2][4][4];
#pragma unroll
    for (int a = 0; a < 2; a++)
#pragma unroll
        for (int b = 0; b < 4; b++)
#pragma unroll
            for (int c = 0; c < 4; c++) acc[a][b][c] = 0.f;

#pragma unroll
    for (int p = 0; p < 3; p++) {
        char* stg = sm + p * G_STAGE;
        const size_t ko = (size_t)p * 32;
        cpasync16(stg + G_AH + soff, gA + goff + ko);
        cpasync16(stg + G_BH + soff, gB + goff + ko);
        CP_COMMIT();
    }

    for (int kt = 0; kt < KT; kt++) {
        CP_WAIT2();
        __syncthreads();
        if (kt + 3 < KT) {
            char* stg = sm + ((kt + 3) & (NSTAGE - 1)) * G_STAGE;
            const size_t ko = (size_t)(kt + 3) * 32;
            cpasync16(stg + G_AH + soff, gA + goff + ko);
            cpasync16(stg + G_BH + soff, gB + goff + ko);
        }
        CP_COMMIT();

        char* stg = sm + (kt & (NSTAGE - 1)) * G_STAGE;
        unsigned short* sA = (unsigned short*)(stg + G_AH);
        unsigned short* sB = (unsigned short*)(stg + G_BH);

#pragma unroll
        for (int ks = 0; ks < 2; ks++) {
            int kb = ks * 16 + lko;
            unsigned af[2][4], bf[2][4];
#pragma unroll
            for (int mt = 0; mt < 2; mt++) {
                int r = (wm * 32 + mt * 16 + lrow) * PS + kb;
                ldm4(af[mt], &sA[r]);
            }
#pragma unroll
            for (int nb = 0; nb < 2; nb++) {
                int r = (wn * 32 + nb * 16 + lrow) * PS + kb;
                ldm4(bf[nb], &sB[r]);
            }
#pragma unroll
            for (int mt = 0; mt < 2; mt++)
#pragma unroll
                for (int nt = 0; nt < 4; nt++) {
                    int nb = nt >> 1, o = nt & 1;
                    mmah(acc[mt][nt], af[mt], bf[nb][o], bf[nb][o + 2]);
                }
        }
    }

    float* Cp = EPI ? (outp + (size_t)bh * Tt * Dd) : (g_S + (size_t)bh * Tt * Tt);
    int rbase = m0 + wm * 32 + (lane >> 2);
    int cbase = n0 + wn * 32 + (lane & 3) * 2;
    float scl = 1.f;
    if (EPI) scl = route[(bh >> 3) * 8 + ((n0 + wn * 32) >> 6)];
#pragma unroll
    for (int mt = 0; mt < 2; mt++)
#pragma unroll
        for (int nt = 0; nt < 4; nt++) {
            int r = rbase + mt * 16, c = cbase + nt * 8;
            *(float2*)&Cp[(size_t)r       * ldc + c] = make_float2(acc[mt][nt][0] * scl, acc[mt][nt][1] * scl);
            *(float2*)&Cp[(size_t)(r + 8) * ldc + c] = make_float2(acc[mt][nt][2] * scl, acc[mt][nt][3] * scl);
        }
}

// ---------------- masked row softmax: fp32 S -> fp16 P ----------------
__global__ __launch_bounds__(256) void softmax_rows(const int* __restrict__ mask) {
    int row = blockIdx.x;
    int q = row & (Tt - 1);
    const float* Srow = g_S + (size_t)row * Tt;
    const int* mrow = mask + (size_t)q * Tt;
    int t = threadIdx.x;
    int lane = t & 31, warp = t >> 5;

    float s[8];
#pragma unroll
    for (int j = 0; j < 8; j++) {
        int k = t + j * 256;
        s[j] = mrow[k] ? -INFINITY : Srow[k];
    }
    float mx = s[0];
#pragma unroll
    for (int j = 1; j < 8; j++) mx = fmaxf(mx, s[j]);
#pragma unroll
    for (int o = 16; o; o >>= 1) mx = fmaxf(mx, __shfl_xor_sync(0xFFFFFFFFu, mx, o));
    __shared__ float red[8];
    if (lane == 0) red[warp] = mx;
    __syncthreads();
    float mall = red[0];
#pragma unroll
    for (int w = 1; w < 8; w++) mall = fmaxf(mall, red[w]);

    float e[8], sum = 0.f;
#pragma unroll
    for (int j = 0; j < 8; j++) {
        e[j] = (s[j] == -INFINITY) ? 0.f : expf(s[j] - mall);
        sum += e[j];
    }
#pragma unroll
    for (int o = 16; o; o >>= 1) sum += __shfl_xor_sync(0xFFFFFFFFu, sum, o);
    __syncthreads();
    if (lane == 0) red[warp] = sum;
    __syncthreads();
    float tot = 0.f;
#pragma unroll
    for (int w = 0; w < 8; w++) tot += red[w];
    float inv = tot > 0.f ? 1.f / tot : 0.f;

#pragma unroll
    for (int j = 0; j < 8; j++) {
        int k = t + j * 256;
        g_P[(size_t)row * Tt + k] = __float2half_rn(e[j] * inv);
    }
}

// ---------------- launch ----------------
extern "C" void kernel_launch(void* const* d_in, const int* in_sizes, int n_in,
                              void* d_out, int out_size) {
    const float* Q     = (const float*)d_in[0];
    const float* K     = (const float*)d_in[1];
    const float* V     = (const float*)d_in[2];
    const float* route = (const float*)d_in[3];
    const int*   mask  = (const int*)d_in[5];
    float* out = (float*)d_out;

    cudaFuncSetAttribute(gemm_nt<0>, cudaFuncAttributeMaxDynamicSharedMemorySize, G_SMEM);
    cudaFuncSetAttribute(gemm_nt<1>, cudaFuncAttributeMaxDynamicSharedMemorySize, G_SMEM);

    convert_qk<<<QKV_ELEMS / 256, 256>>>(Q, K, route);
    convert_vt<<<dim3(Tt / 32, Dd / 32, BHn), 256>>>(V);
    gemm_nt<0><<<dim3(Tt / 128, Tt / 128, BHn), 512, G_SMEM>>>(nullptr, route);
    softmax_rows<<<BHn * Tt, 256>>>(mask);
    gemm_nt<1><<<dim3(Dd / 128, Tt / 128, BHn), 512, G_SMEM>>>(out, route);
}